// round 1
// baseline (speedup 1.0000x reference)
#include <cuda_runtime.h>
#include <cuda_bf16.h>

#define N_NODES 50000
#define N_EDGES 600000
#define D 128

// ---------------- scratch (static device globals; no allocation) ----------
__device__ float g_dis[N_NODES];                 // deg^{-1/2}
__device__ int   g_counts[N_NODES];              // in-degree histogram
__device__ int   g_offsets[N_NODES + 1];         // CSR row offsets (by dst)
__device__ int   g_cursor[N_NODES];              // scatter cursors
__device__ int   g_csr_src[N_EDGES];             // src per CSR slot
__device__ float g_csr_norm[N_EDGES];            // dis[src]*dis[dst] per CSR slot
__device__ float g_bufA[(size_t)N_NODES * D];    // hw buffer
__device__ float g_bufB[(size_t)N_NODES * D];    // activation buffer
__device__ float g_hw3[N_NODES];                 // layer-3 GEMV result

// ---------------- preprocessing ------------------------------------------
__global__ void init_counts_kernel() {
    int i = blockIdx.x * blockDim.x + threadIdx.x;
    if (i < N_NODES) g_counts[i] = 0;
}

__global__ void hist_kernel(const int* __restrict__ dst) {
    int e = blockIdx.x * blockDim.x + threadIdx.x;
    if (e < N_EDGES) atomicAdd(&g_counts[dst[e]], 1);
}

// single-block inclusive scan over 50k counts -> offsets
__global__ void scan_kernel() {
    __shared__ int sh[1024];
    __shared__ int carry_sh;
    if (threadIdx.x == 0) { carry_sh = 0; g_offsets[0] = 0; }
    __syncthreads();
    for (int base = 0; base < N_NODES; base += 1024) {
        int i = base + threadIdx.x;
        int v = (i < N_NODES) ? g_counts[i] : 0;
        sh[threadIdx.x] = v;
        __syncthreads();
        #pragma unroll
        for (int off = 1; off < 1024; off <<= 1) {
            int t = (threadIdx.x >= off) ? sh[threadIdx.x - off] : 0;
            __syncthreads();
            sh[threadIdx.x] += t;
            __syncthreads();
        }
        if (i < N_NODES) g_offsets[i + 1] = sh[threadIdx.x] + carry_sh;
        __syncthreads();
        if (threadIdx.x == 0) carry_sh += sh[1023];
        __syncthreads();
    }
}

__global__ void dis_cursor_kernel() {
    int i = blockIdx.x * blockDim.x + threadIdx.x;
    if (i < N_NODES) {
        g_dis[i]    = rsqrtf((float)g_counts[i] + 1.0f);
        g_cursor[i] = g_offsets[i];
    }
}

__global__ void scatter_kernel(const int* __restrict__ src,
                               const int* __restrict__ dst) {
    int e = blockIdx.x * blockDim.x + threadIdx.x;
    if (e < N_EDGES) {
        int s = src[e], d = dst[e];
        int pos = atomicAdd(&g_cursor[d], 1);
        g_csr_src[pos]  = s;
        g_csr_norm[pos] = g_dis[s] * g_dis[d];
    }
}

// ---------------- fp32 GEMM: OUT[M,128] = X[M,128] @ W[128,128] -----------
#define BM 64
#define BN 128
#define BK 32
#define TM 8
#define TN 4

__global__ __launch_bounds__(256)
void gemm128_kernel(const float* __restrict__ X, const float* __restrict__ W,
                    float* __restrict__ OUT, int M) {
    __shared__ float xs[BM][BK + 1];
    __shared__ float ws[BK][BN];

    int tid = threadIdx.x;
    int block_row = blockIdx.x * BM;
    int trow = tid >> 5;      // 0..7
    int tcol = tid & 31;      // 0..31

    float acc[TM][TN];
    #pragma unroll
    for (int i = 0; i < TM; i++)
        #pragma unroll
        for (int j = 0; j < TN; j++) acc[i][j] = 0.0f;

    for (int kc = 0; kc < D; kc += BK) {
        // X tile: 64 x 32 as float4 (512 float4, 2 per thread)
        #pragma unroll
        for (int i = tid; i < BM * BK / 4; i += 256) {
            int r  = i >> 3;          // / (BK/4)
            int c4 = i & 7;
            int gr = block_row + r;
            float4 v = make_float4(0.f, 0.f, 0.f, 0.f);
            if (gr < M)
                v = *(const float4*)(X + (size_t)gr * D + kc + c4 * 4);
            xs[r][c4 * 4 + 0] = v.x; xs[r][c4 * 4 + 1] = v.y;
            xs[r][c4 * 4 + 2] = v.z; xs[r][c4 * 4 + 3] = v.w;
        }
        // W tile: 32 x 128 as float4 (1024 float4, 4 per thread)
        #pragma unroll
        for (int i = tid; i < BK * BN / 4; i += 256) {
            int r  = i >> 5;          // / (BN/4)
            int c4 = i & 31;
            *(float4*)&ws[r][c4 * 4] =
                *(const float4*)(W + (size_t)(kc + r) * BN + c4 * 4);
        }
        __syncthreads();

        #pragma unroll
        for (int k = 0; k < BK; k++) {
            float a[TM], b[TN];
            #pragma unroll
            for (int i = 0; i < TM; i++) a[i] = xs[trow * TM + i][k];
            #pragma unroll
            for (int j = 0; j < TN; j++) b[j] = ws[k][tcol * TN + j];
            #pragma unroll
            for (int i = 0; i < TM; i++)
                #pragma unroll
                for (int j = 0; j < TN; j++) acc[i][j] += a[i] * b[j];
        }
        __syncthreads();
    }

    #pragma unroll
    for (int i = 0; i < TM; i++) {
        int gr = block_row + trow * TM + i;
        if (gr < M) {
            float4 v = make_float4(acc[i][0], acc[i][1], acc[i][2], acc[i][3]);
            *(float4*)(OUT + (size_t)gr * D + tcol * TN) = v;
        }
    }
}

// ---------------- aggregation (warp per node), F=128 ----------------------
__global__ __launch_bounds__(256)
void agg128_kernel(const float* __restrict__ HW, const float* __restrict__ bias,
                   float* __restrict__ OUT) {
    int warp = (blockIdx.x * blockDim.x + threadIdx.x) >> 5;
    int lane = threadIdx.x & 31;
    if (warp >= N_NODES) return;
    int node = warp;

    float sn = g_dis[node]; sn *= sn;   // self_norm = 1/deg
    float4 acc = ((const float4*)(HW + (size_t)node * D))[lane];
    acc.x *= sn; acc.y *= sn; acc.z *= sn; acc.w *= sn;

    int beg = g_offsets[node], end = g_offsets[node + 1];
    for (int e = beg; e < end; e++) {
        int s   = __ldg(&g_csr_src[e]);
        float w = __ldg(&g_csr_norm[e]);
        float4 v = ((const float4*)(HW + (size_t)s * D))[lane];
        acc.x += v.x * w; acc.y += v.y * w; acc.z += v.z * w; acc.w += v.w * w;
    }
    float4 b = ((const float4*)bias)[lane];
    acc.x = fmaxf(acc.x + b.x, 0.f);
    acc.y = fmaxf(acc.y + b.y, 0.f);
    acc.z = fmaxf(acc.z + b.z, 0.f);
    acc.w = fmaxf(acc.w + b.w, 0.f);
    ((float4*)(OUT + (size_t)node * D))[lane] = acc;
}

// ---------------- layer 3: GEMV (128 -> 1), then scalar aggregation -------
__global__ __launch_bounds__(256)
void gemv3_kernel(const float* __restrict__ H, const float* __restrict__ W3) {
    int warp = (blockIdx.x * blockDim.x + threadIdx.x) >> 5;
    int lane = threadIdx.x & 31;
    if (warp >= N_NODES) return;
    const float* row = H + (size_t)warp * D;
    float acc = 0.f;
    #pragma unroll
    for (int j = 0; j < 4; j++) {
        int k = lane + 32 * j;
        acc += row[k] * __ldg(&W3[k]);
    }
    #pragma unroll
    for (int off = 16; off > 0; off >>= 1)
        acc += __shfl_down_sync(0xFFFFFFFFu, acc, off);
    if (lane == 0) g_hw3[warp] = acc;
}

__global__ void agg3_kernel(const float* __restrict__ b3, float* __restrict__ OUT) {
    int node = blockIdx.x * blockDim.x + threadIdx.x;
    if (node >= N_NODES) return;
    float sn = g_dis[node]; sn *= sn;
    float acc = g_hw3[node] * sn;
    int beg = g_offsets[node], end = g_offsets[node + 1];
    for (int e = beg; e < end; e++)
        acc += g_hw3[__ldg(&g_csr_src[e])] * __ldg(&g_csr_norm[e]);
    OUT[node] = fmaxf(acc + b3[0], 0.f);
}

// ---------------- launch ---------------------------------------------------
extern "C" void kernel_launch(void* const* d_in, const int* in_sizes, int n_in,
                              void* d_out, int out_size) {
    const float* x   = (const float*)d_in[0];
    const int*   ei  = (const int*)d_in[1];
    const float* W1  = (const float*)d_in[2];
    const float* b1  = (const float*)d_in[3];
    const float* W2  = (const float*)d_in[4];
    const float* b2  = (const float*)d_in[5];
    const float* W3  = (const float*)d_in[6];
    const float* b3  = (const float*)d_in[7];
    float* out = (float*)d_out;

    const int* src = ei;
    const int* dst = ei + N_EDGES;

    float* bufA; cudaGetSymbolAddress((void**)&bufA, g_bufA);
    float* bufB; cudaGetSymbolAddress((void**)&bufB, g_bufB);

    int nb_nodes = (N_NODES + 255) / 256;
    int nb_edges = (N_EDGES + 255) / 256;
    int nb_warp  = (N_NODES * 32 + 255) / 256;   // warp-per-node kernels
    int nb_gemm  = (N_NODES + BM - 1) / BM;

    // preprocessing: CSR by dst + norms (recomputed every launch; deterministic)
    init_counts_kernel<<<nb_nodes, 256>>>();
    hist_kernel<<<nb_edges, 256>>>(dst);
    scan_kernel<<<1, 1024>>>();
    dis_cursor_kernel<<<nb_nodes, 256>>>();
    scatter_kernel<<<nb_edges, 256>>>(src, dst);

    // layer 1
    gemm128_kernel<<<nb_gemm, 256>>>(x, W1, bufA, N_NODES);
    agg128_kernel<<<nb_warp, 256>>>(bufA, b1, bufB);
    // layer 2
    gemm128_kernel<<<nb_gemm, 256>>>(bufB, W2, bufA, N_NODES);
    agg128_kernel<<<nb_warp, 256>>>(bufA, b2, bufB);
    // layer 3
    gemv3_kernel<<<nb_warp, 256>>>(bufB, W3);
    agg3_kernel<<<nb_nodes, 256>>>(b3, out);
}

// round 2
// speedup vs baseline: 1.3880x; 1.3880x over previous
#include <cuda_runtime.h>
#include <cuda_bf16.h>
#include <cstdint>

#define N_NODES 50000
#define N_EDGES 600000
#define D 128

// ---------------- scratch (static device globals; no allocation) ----------
__device__ float g_dis[N_NODES];                 // deg^{-1/2}
__device__ int   g_counts[N_NODES];              // in-degree histogram
__device__ int   g_base[N_NODES];                // CSR chunk base (unordered)
__device__ int   g_cursor[N_NODES];              // scatter cursors
__device__ int   g_total;                        // running total for base alloc
__device__ int   g_csr_src[N_EDGES];             // src per CSR slot
__device__ float g_bufA[(size_t)N_NODES * D];    // hw' buffer (dis-scaled)
__device__ float g_bufB[(size_t)N_NODES * D];    // activation buffer
__device__ float g_hw3[N_NODES];                 // layer-3 GEMV result (dis-scaled)

// ---------------- preprocessing ------------------------------------------
__global__ void init_kernel() {
    int i = blockIdx.x * blockDim.x + threadIdx.x;
    if (i < N_NODES) g_counts[i] = 0;
    if (i == 0) g_total = 0;
}

__global__ void hist_kernel(const int* __restrict__ dst) {
    int e = blockIdx.x * blockDim.x + threadIdx.x;
    if (e < N_EDGES) atomicAdd(&g_counts[dst[e]], 1);
}

// per-block prefix over counts + one atomic per block for the base.
// CSR chunks are NOT node-ordered (base order depends on atomic order) but each
// node owns a contiguous chunk, which is all aggregation needs.
__global__ void prefix_kernel() {
    __shared__ int sh[256];
    __shared__ int block_base;
    int i = blockIdx.x * 256 + threadIdx.x;
    int c = (i < N_NODES) ? g_counts[i] : 0;
    int v = c;
    sh[threadIdx.x] = v;
    __syncthreads();
    #pragma unroll
    for (int off = 1; off < 256; off <<= 1) {
        int t = (threadIdx.x >= off) ? sh[threadIdx.x - off] : 0;
        __syncthreads();
        v += t;
        sh[threadIdx.x] = v;
        __syncthreads();
    }
    if (threadIdx.x == 255) block_base = atomicAdd(&g_total, v);
    __syncthreads();
    if (i < N_NODES) {
        int base = block_base + v - c;  // exclusive prefix within block
        g_base[i]   = base;
        g_cursor[i] = base;
        g_dis[i]    = rsqrtf((float)c + 1.0f);
    }
}

__global__ void scatter_kernel(const int* __restrict__ src,
                               const int* __restrict__ dst) {
    int e = blockIdx.x * blockDim.x + threadIdx.x;
    if (e < N_EDGES) {
        int pos = atomicAdd(&g_cursor[dst[e]], 1);
        g_csr_src[pos] = src[e];
    }
}

// ---------------- 3xTF32 tensor-core GEMM --------------------------------
// OUT[r][c] = (X[M,128] @ W[128,128])[r][c] * g_dis[r]
// block tile 128(M) x 64(N); 8 warps in 4x2 grid; warp tile 32x32;
// mma.sync.aligned.m16n8k8.row.col.f32.tf32.tf32.f32, hi/lo split (3 mmas).

__device__ __forceinline__ uint32_t f2tf32(float x) {
    uint32_t r;
    asm("cvt.rna.tf32.f32 %0, %1;" : "=r"(r) : "f"(x));
    return r;
}

__device__ __forceinline__ void split_tf32(float x, uint32_t& hi, uint32_t& lo) {
    hi = f2tf32(x);
    float l = x - __uint_as_float(hi);
    lo = f2tf32(l);
}

__device__ __forceinline__ void mma_tf32(float4& d, const uint32_t* a, const uint32_t* b) {
    asm volatile(
        "mma.sync.aligned.m16n8k8.row.col.f32.tf32.tf32.f32 "
        "{%0,%1,%2,%3}, {%4,%5,%6,%7}, {%8,%9}, {%0,%1,%2,%3};"
        : "+f"(d.x), "+f"(d.y), "+f"(d.z), "+f"(d.w)
        : "r"(a[0]), "r"(a[1]), "r"(a[2]), "r"(a[3]), "r"(b[0]), "r"(b[1]));
}

#define PITCH 20   // floats; (20*r + c) % 32 is conflict-free for the frag patterns

__global__ __launch_bounds__(256, 2)
void gemm_tf32_kernel(const float* __restrict__ X, const float* __restrict__ W,
                      float* __restrict__ OUT, int M) {
    __shared__ uint32_t As_hi[128 * PITCH];
    __shared__ uint32_t As_lo[128 * PITCH];
    __shared__ uint32_t BT_hi[64 * PITCH];   // B^T: [n][k]
    __shared__ uint32_t BT_lo[64 * PITCH];

    int tid = threadIdx.x;
    int wid = tid >> 5, lane = tid & 31;
    int wm = wid >> 1, wn = wid & 1;         // 4 x 2 warp grid
    int g = lane >> 2, t = lane & 3;
    int block_row = blockIdx.x * 128;
    int n0 = blockIdx.y * 64;

    float4 acc[2][4];
    #pragma unroll
    for (int mt = 0; mt < 2; mt++)
        #pragma unroll
        for (int nt = 0; nt < 4; nt++)
            acc[mt][nt] = make_float4(0.f, 0.f, 0.f, 0.f);

    for (int kc = 0; kc < D; kc += 16) {
        // A chunk: 128 rows x 16 cols  (512 float4, 2 per thread)
        #pragma unroll
        for (int i = tid; i < 512; i += 256) {
            int r = i >> 2, c4 = (i & 3) * 4;
            int gr = block_row + r;
            float4 v = make_float4(0.f, 0.f, 0.f, 0.f);
            if (gr < M) v = *(const float4*)(X + (size_t)gr * D + kc + c4);
            uint32_t h0, l0, h1, l1, h2, l2, h3, l3;
            split_tf32(v.x, h0, l0); split_tf32(v.y, h1, l1);
            split_tf32(v.z, h2, l2); split_tf32(v.w, h3, l3);
            uint32_t* ph = &As_hi[r * PITCH + c4];
            uint32_t* pl = &As_lo[r * PITCH + c4];
            *(uint4*)ph = make_uint4(h0, h1, h2, h3);
            *(uint4*)pl = make_uint4(l0, l1, l2, l3);
        }
        // B chunk: 16 rows x 64 cols, stored transposed (256 float4, 1 per thread)
        {
            int r = tid >> 4, c4 = (tid & 15) * 4;
            float4 v = *(const float4*)(W + (size_t)(kc + r) * D + n0 + c4);
            uint32_t h, l;
            split_tf32(v.x, h, l); BT_hi[(c4 + 0) * PITCH + r] = h; BT_lo[(c4 + 0) * PITCH + r] = l;
            split_tf32(v.y, h, l); BT_hi[(c4 + 1) * PITCH + r] = h; BT_lo[(c4 + 1) * PITCH + r] = l;
            split_tf32(v.z, h, l); BT_hi[(c4 + 2) * PITCH + r] = h; BT_lo[(c4 + 2) * PITCH + r] = l;
            split_tf32(v.w, h, l); BT_hi[(c4 + 3) * PITCH + r] = h; BT_lo[(c4 + 3) * PITCH + r] = l;
        }
        __syncthreads();

        #pragma unroll
        for (int k8 = 0; k8 < 2; k8++) {
            int kb = k8 * 8;
            uint32_t ah[2][4], al[2][4];
            #pragma unroll
            for (int mt = 0; mt < 2; mt++) {
                int base = (wm * 32 + mt * 16 + g) * PITCH + kb + t;
                ah[mt][0] = As_hi[base];
                ah[mt][1] = As_hi[base + 8 * PITCH];
                ah[mt][2] = As_hi[base + 4];
                ah[mt][3] = As_hi[base + 8 * PITCH + 4];
                al[mt][0] = As_lo[base];
                al[mt][1] = As_lo[base + 8 * PITCH];
                al[mt][2] = As_lo[base + 4];
                al[mt][3] = As_lo[base + 8 * PITCH + 4];
            }
            uint32_t bh[4][2], bl[4][2];
            #pragma unroll
            for (int nt = 0; nt < 4; nt++) {
                int base = (wn * 32 + nt * 8 + g) * PITCH + kb + t;
                bh[nt][0] = BT_hi[base];
                bh[nt][1] = BT_hi[base + 4];
                bl[nt][0] = BT_lo[base];
                bl[nt][1] = BT_lo[base + 4];
            }
            #pragma unroll
            for (int mt = 0; mt < 2; mt++)
                #pragma unroll
                for (int nt = 0; nt < 4; nt++) {
                    mma_tf32(acc[mt][nt], ah[mt], bh[nt]);
                    mma_tf32(acc[mt][nt], ah[mt], bl[nt]);
                    mma_tf32(acc[mt][nt], al[mt], bh[nt]);
                }
        }
        __syncthreads();
    }

    // epilogue: scale rows by dis, store
    #pragma unroll
    for (int mt = 0; mt < 2; mt++) {
        int r0 = block_row + wm * 32 + mt * 16 + g;
        int r1 = r0 + 8;
        float d0 = (r0 < M) ? g_dis[r0] : 0.f;
        float d1 = (r1 < M) ? g_dis[r1] : 0.f;
        #pragma unroll
        for (int nt = 0; nt < 4; nt++) {
            int col = n0 + wn * 32 + nt * 8 + 2 * t;
            float4 c = acc[mt][nt];
            if (r0 < M) *(float2*)(OUT + (size_t)r0 * D + col) = make_float2(c.x * d0, c.y * d0);
            if (r1 < M) *(float2*)(OUT + (size_t)r1 * D + col) = make_float2(c.z * d1, c.w * d1);
        }
    }
}

// ---------------- aggregation (warp per node), F=128 ----------------------
// HW holds hw' = hw * dis (row-scaled).  out = relu(dis[d]*(sum_src hw'[s] + hw'[d]) + b)
__global__ __launch_bounds__(256)
void agg128_kernel(const float* __restrict__ HW, const float* __restrict__ bias,
                   float* __restrict__ OUT) {
    int warp = (blockIdx.x * blockDim.x + threadIdx.x) >> 5;
    int lane = threadIdx.x & 31;
    if (warp >= N_NODES) return;
    int node = warp;

    float4 acc = ((const float4*)(HW + (size_t)node * D))[lane];  // self term hw'[d]

    int beg = g_base[node];
    int end = beg + g_counts[node];
    int e = beg;
    for (; e + 2 <= end; e += 2) {
        int s0 = __ldg(&g_csr_src[e]);
        int s1 = __ldg(&g_csr_src[e + 1]);
        float4 v0 = ((const float4*)(HW + (size_t)s0 * D))[lane];
        float4 v1 = ((const float4*)(HW + (size_t)s1 * D))[lane];
        acc.x += v0.x; acc.y += v0.y; acc.z += v0.z; acc.w += v0.w;
        acc.x += v1.x; acc.y += v1.y; acc.z += v1.z; acc.w += v1.w;
    }
    if (e < end) {
        int s = __ldg(&g_csr_src[e]);
        float4 v = ((const float4*)(HW + (size_t)s * D))[lane];
        acc.x += v.x; acc.y += v.y; acc.z += v.z; acc.w += v.w;
    }

    float dn = g_dis[node];
    float4 b = ((const float4*)bias)[lane];
    acc.x = fmaxf(acc.x * dn + b.x, 0.f);
    acc.y = fmaxf(acc.y * dn + b.y, 0.f);
    acc.z = fmaxf(acc.z * dn + b.z, 0.f);
    acc.w = fmaxf(acc.w * dn + b.w, 0.f);
    ((float4*)(OUT + (size_t)node * D))[lane] = acc;
}

// ---------------- layer 3: GEMV (128 -> 1, dis-scaled), scalar agg --------
__global__ __launch_bounds__(256)
void gemv3_kernel(const float* __restrict__ H, const float* __restrict__ W3) {
    int warp = (blockIdx.x * blockDim.x + threadIdx.x) >> 5;
    int lane = threadIdx.x & 31;
    if (warp >= N_NODES) return;
    const float* row = H + (size_t)warp * D;
    float acc = 0.f;
    #pragma unroll
    for (int j = 0; j < 4; j++) {
        int k = lane + 32 * j;
        acc += row[k] * __ldg(&W3[k]);
    }
    #pragma unroll
    for (int off = 16; off > 0; off >>= 1)
        acc += __shfl_down_sync(0xFFFFFFFFu, acc, off);
    if (lane == 0) g_hw3[warp] = acc * g_dis[warp];
}

__global__ void agg3_kernel(const float* __restrict__ b3, float* __restrict__ OUT) {
    int node = blockIdx.x * blockDim.x + threadIdx.x;
    if (node >= N_NODES) return;
    float acc = g_hw3[node];
    int beg = g_base[node];
    int end = beg + g_counts[node];
    for (int e = beg; e < end; e++)
        acc += g_hw3[__ldg(&g_csr_src[e])];
    OUT[node] = fmaxf(acc * g_dis[node] + b3[0], 0.f);
}

// ---------------- launch ---------------------------------------------------
extern "C" void kernel_launch(void* const* d_in, const int* in_sizes, int n_in,
                              void* d_out, int out_size) {
    const float* x  = (const float*)d_in[0];
    const int*   ei = (const int*)d_in[1];
    const float* W1 = (const float*)d_in[2];
    const float* b1 = (const float*)d_in[3];
    const float* W2 = (const float*)d_in[4];
    const float* b2 = (const float*)d_in[5];
    const float* W3 = (const float*)d_in[6];
    const float* b3 = (const float*)d_in[7];
    float* out = (float*)d_out;

    const int* src = ei;
    const int* dst = ei + N_EDGES;

    float* bufA; cudaGetSymbolAddress((void**)&bufA, g_bufA);
    float* bufB; cudaGetSymbolAddress((void**)&bufB, g_bufB);

    int nb_nodes = (N_NODES + 255) / 256;
    int nb_edges = (N_EDGES + 255) / 256;
    int nb_warp  = (N_NODES * 32 + 255) / 256;
    dim3 gemm_grid((N_NODES + 127) / 128, 2);

    // preprocessing: unordered CSR by dst
    init_kernel<<<nb_nodes, 256>>>();
    hist_kernel<<<nb_edges, 256>>>(dst);
    prefix_kernel<<<nb_nodes, 256>>>();
    scatter_kernel<<<nb_edges, 256>>>(src, dst);

    // layer 1
    gemm_tf32_kernel<<<gemm_grid, 256>>>(x, W1, bufA, N_NODES);
    agg128_kernel<<<nb_warp, 256>>>(bufA, b1, bufB);
    // layer 2
    gemm_tf32_kernel<<<gemm_grid, 256>>>(bufB, W2, bufA, N_NODES);
    agg128_kernel<<<nb_warp, 256>>>(bufA, b2, bufB);
    // layer 3
    gemv3_kernel<<<nb_warp, 256>>>(bufB, W3);
    agg3_kernel<<<nb_nodes, 256>>>(b3, out);
}

// round 3
// speedup vs baseline: 1.4601x; 1.0519x over previous
#include <cuda_runtime.h>
#include <cuda_fp16.h>
#include <cstdint>

#define N_NODES 50000
#define N_EDGES 600000
#define D 128

// ---------------- scratch (static device globals; no allocation) ----------
__device__ float  g_dis[N_NODES];                // deg^{-1/2}
__device__ int    g_counts[N_NODES];             // in-degree histogram
__device__ int    g_base[N_NODES];               // CSR chunk base (unordered)
__device__ int    g_cursor[N_NODES];             // scatter cursors
__device__ int    g_total;                       // running total for base alloc
__device__ int    g_csr_src[N_EDGES];            // src per CSR slot
__device__ __half g_hw[(size_t)N_NODES * D];     // hw' buffer (dis-scaled, fp16)
__device__ float  g_act[(size_t)N_NODES * D];    // activation buffer (fp32)
__device__ float  g_hw3[N_NODES];                // layer-3 GEMV result (dis-scaled)

// ---------------- preprocessing ------------------------------------------
__global__ void hist_kernel(const int* __restrict__ dst) {
    int i = blockIdx.x * blockDim.x + threadIdx.x;   // handles 4 edges
    if (i * 4 < N_EDGES) {
        int4 d4 = *(const int4*)(dst + i * 4);
        atomicAdd(&g_counts[d4.x], 1);
        atomicAdd(&g_counts[d4.y], 1);
        atomicAdd(&g_counts[d4.z], 1);
        atomicAdd(&g_counts[d4.w], 1);
    }
}

// per-block prefix over counts + one atomic per block for the base.
// CSR chunks are NOT node-ordered but each node owns a contiguous chunk.
__global__ void prefix_kernel() {
    __shared__ int sh[256];
    __shared__ int block_base;
    int i = blockIdx.x * 256 + threadIdx.x;
    int c = (i < N_NODES) ? g_counts[i] : 0;
    int v = c;
    sh[threadIdx.x] = v;
    __syncthreads();
    #pragma unroll
    for (int off = 1; off < 256; off <<= 1) {
        int t = (threadIdx.x >= off) ? sh[threadIdx.x - off] : 0;
        __syncthreads();
        v += t;
        sh[threadIdx.x] = v;
        __syncthreads();
    }
    if (threadIdx.x == 255) block_base = atomicAdd(&g_total, v);
    __syncthreads();
    if (i < N_NODES) {
        int base = block_base + v - c;  // exclusive prefix within block
        g_base[i]   = base;
        g_cursor[i] = base;
        g_dis[i]    = rsqrtf((float)c + 1.0f);
    }
}

__global__ void scatter_kernel(const int* __restrict__ src,
                               const int* __restrict__ dst) {
    int i = blockIdx.x * blockDim.x + threadIdx.x;
    if (i * 4 < N_EDGES) {
        int4 s4 = *(const int4*)(src + i * 4);
        int4 d4 = *(const int4*)(dst + i * 4);
        int p0 = atomicAdd(&g_cursor[d4.x], 1);
        int p1 = atomicAdd(&g_cursor[d4.y], 1);
        int p2 = atomicAdd(&g_cursor[d4.z], 1);
        int p3 = atomicAdd(&g_cursor[d4.w], 1);
        g_csr_src[p0] = s4.x;
        g_csr_src[p1] = s4.y;
        g_csr_src[p2] = s4.z;
        g_csr_src[p3] = s4.w;
    }
}

// ---------------- 3xTF32 tensor-core GEMM --------------------------------
// OUT(fp16)[r][c] = (X[M,128] @ W[128,128])[r][c] * g_dis[r]

__device__ __forceinline__ uint32_t f2tf32(float x) {
    uint32_t r;
    asm("cvt.rna.tf32.f32 %0, %1;" : "=r"(r) : "f"(x));
    return r;
}

__device__ __forceinline__ void split_tf32(float x, uint32_t& hi, uint32_t& lo) {
    hi = f2tf32(x);
    float l = x - __uint_as_float(hi);
    lo = f2tf32(l);
}

__device__ __forceinline__ void mma_tf32(float4& d, const uint32_t* a, const uint32_t* b) {
    asm volatile(
        "mma.sync.aligned.m16n8k8.row.col.f32.tf32.tf32.f32 "
        "{%0,%1,%2,%3}, {%4,%5,%6,%7}, {%8,%9}, {%0,%1,%2,%3};"
        : "+f"(d.x), "+f"(d.y), "+f"(d.z), "+f"(d.w)
        : "r"(a[0]), "r"(a[1]), "r"(a[2]), "r"(a[3]), "r"(b[0]), "r"(b[1]));
}

#define PITCH 20

__global__ __launch_bounds__(256, 2)
void gemm_tf32_kernel(const float* __restrict__ X, const float* __restrict__ W,
                      __half* __restrict__ OUT, int M) {
    __shared__ uint32_t As_hi[128 * PITCH];
    __shared__ uint32_t As_lo[128 * PITCH];
    __shared__ uint32_t BT_hi[64 * PITCH];   // B^T: [n][k]
    __shared__ uint32_t BT_lo[64 * PITCH];

    int tid = threadIdx.x;
    int wid = tid >> 5, lane = tid & 31;
    int wm = wid >> 1, wn = wid & 1;         // 4 x 2 warp grid
    int g = lane >> 2, t = lane & 3;
    int block_row = blockIdx.x * 128;
    int n0 = blockIdx.y * 64;

    float4 acc[2][4];
    #pragma unroll
    for (int mt = 0; mt < 2; mt++)
        #pragma unroll
        for (int nt = 0; nt < 4; nt++)
            acc[mt][nt] = make_float4(0.f, 0.f, 0.f, 0.f);

    for (int kc = 0; kc < D; kc += 16) {
        #pragma unroll
        for (int i = tid; i < 512; i += 256) {
            int r = i >> 2, c4 = (i & 3) * 4;
            int gr = block_row + r;
            float4 v = make_float4(0.f, 0.f, 0.f, 0.f);
            if (gr < M) v = *(const float4*)(X + (size_t)gr * D + kc + c4);
            uint32_t h0, l0, h1, l1, h2, l2, h3, l3;
            split_tf32(v.x, h0, l0); split_tf32(v.y, h1, l1);
            split_tf32(v.z, h2, l2); split_tf32(v.w, h3, l3);
            uint32_t* ph = &As_hi[r * PITCH + c4];
            uint32_t* pl = &As_lo[r * PITCH + c4];
            *(uint4*)ph = make_uint4(h0, h1, h2, h3);
            *(uint4*)pl = make_uint4(l0, l1, l2, l3);
        }
        {
            int r = tid >> 4, c4 = (tid & 15) * 4;
            float4 v = *(const float4*)(W + (size_t)(kc + r) * D + n0 + c4);
            uint32_t h, l;
            split_tf32(v.x, h, l); BT_hi[(c4 + 0) * PITCH + r] = h; BT_lo[(c4 + 0) * PITCH + r] = l;
            split_tf32(v.y, h, l); BT_hi[(c4 + 1) * PITCH + r] = h; BT_lo[(c4 + 1) * PITCH + r] = l;
            split_tf32(v.z, h, l); BT_hi[(c4 + 2) * PITCH + r] = h; BT_lo[(c4 + 2) * PITCH + r] = l;
            split_tf32(v.w, h, l); BT_hi[(c4 + 3) * PITCH + r] = h; BT_lo[(c4 + 3) * PITCH + r] = l;
        }
        __syncthreads();

        #pragma unroll
        for (int k8 = 0; k8 < 2; k8++) {
            int kb = k8 * 8;
            uint32_t ah[2][4], al[2][4];
            #pragma unroll
            for (int mt = 0; mt < 2; mt++) {
                int base = (wm * 32 + mt * 16 + g) * PITCH + kb + t;
                ah[mt][0] = As_hi[base];
                ah[mt][1] = As_hi[base + 8 * PITCH];
                ah[mt][2] = As_hi[base + 4];
                ah[mt][3] = As_hi[base + 8 * PITCH + 4];
                al[mt][0] = As_lo[base];
                al[mt][1] = As_lo[base + 8 * PITCH];
                al[mt][2] = As_lo[base + 4];
                al[mt][3] = As_lo[base + 8 * PITCH + 4];
            }
            uint32_t bh[4][2], bl[4][2];
            #pragma unroll
            for (int nt = 0; nt < 4; nt++) {
                int base = (wn * 32 + nt * 8 + g) * PITCH + kb + t;
                bh[nt][0] = BT_hi[base];
                bh[nt][1] = BT_hi[base + 4];
                bl[nt][0] = BT_lo[base];
                bl[nt][1] = BT_lo[base + 4];
            }
            #pragma unroll
            for (int mt = 0; mt < 2; mt++)
                #pragma unroll
                for (int nt = 0; nt < 4; nt++) {
                    mma_tf32(acc[mt][nt], ah[mt], bh[nt]);
                    mma_tf32(acc[mt][nt], ah[mt], bl[nt]);
                    mma_tf32(acc[mt][nt], al[mt], bh[nt]);
                }
        }
        __syncthreads();
    }

    // epilogue: scale rows by dis, store fp16
    #pragma unroll
    for (int mt = 0; mt < 2; mt++) {
        int r0 = block_row + wm * 32 + mt * 16 + g;
        int r1 = r0 + 8;
        float d0 = (r0 < M) ? g_dis[r0] : 0.f;
        float d1 = (r1 < M) ? g_dis[r1] : 0.f;
        #pragma unroll
        for (int nt = 0; nt < 4; nt++) {
            int col = n0 + wn * 32 + nt * 8 + 2 * t;
            float4 c = acc[mt][nt];
            if (r0 < M)
                *(__half2*)(OUT + (size_t)r0 * D + col) = __floats2half2_rn(c.x * d0, c.y * d0);
            if (r1 < M)
                *(__half2*)(OUT + (size_t)r1 * D + col) = __floats2half2_rn(c.z * d1, c.w * d1);
        }
    }
}

// ---------------- aggregation (warp per node), F=128, fp16 gathers --------
// HW holds hw' = hw * dis (fp16).  act = relu(dis[d]*(sum_src hw'[s] + hw'[d]) + b)
// FUSE_GEMV: instead of writing act, write g_hw3[node] = dot(act, W3) * dis[node]
template <bool FUSE_GEMV>
__global__ __launch_bounds__(256)
void agg128_kernel(const __half* __restrict__ HW, const float* __restrict__ bias,
                   float* __restrict__ OUT, const float* __restrict__ W3) {
    int warp = (blockIdx.x * blockDim.x + threadIdx.x) >> 5;
    int lane = threadIdx.x & 31;
    if (warp >= N_NODES) return;
    int node = warp;

    // lane owns features [4*lane, 4*lane+4): one uint2 = 4 halves per row
    const uint2* rowp = (const uint2*)(HW + (size_t)node * D) + lane;
    uint2 sv = *rowp;
    float2 a0 = __half22float2(*(const __half2*)&sv.x);
    float2 a1 = __half22float2(*(const __half2*)&sv.y);
    float4 acc = make_float4(a0.x, a0.y, a1.x, a1.y);

    int beg = g_base[node];
    int end = beg + g_counts[node];
    int e = beg;
    for (; e + 2 <= end; e += 2) {
        int s0 = __ldg(&g_csr_src[e]);
        int s1 = __ldg(&g_csr_src[e + 1]);
        uint2 v0 = *((const uint2*)(HW + (size_t)s0 * D) + lane);
        uint2 v1 = *((const uint2*)(HW + (size_t)s1 * D) + lane);
        float2 f00 = __half22float2(*(const __half2*)&v0.x);
        float2 f01 = __half22float2(*(const __half2*)&v0.y);
        float2 f10 = __half22float2(*(const __half2*)&v1.x);
        float2 f11 = __half22float2(*(const __half2*)&v1.y);
        acc.x += f00.x + f10.x; acc.y += f00.y + f10.y;
        acc.z += f01.x + f11.x; acc.w += f01.y + f11.y;
    }
    if (e < end) {
        int s = __ldg(&g_csr_src[e]);
        uint2 v = *((const uint2*)(HW + (size_t)s * D) + lane);
        float2 f0 = __half22float2(*(const __half2*)&v.x);
        float2 f1 = __half22float2(*(const __half2*)&v.y);
        acc.x += f0.x; acc.y += f0.y; acc.z += f1.x; acc.w += f1.y;
    }

    float dn = g_dis[node];
    float4 b = ((const float4*)bias)[lane];
    acc.x = fmaxf(acc.x * dn + b.x, 0.f);
    acc.y = fmaxf(acc.y * dn + b.y, 0.f);
    acc.z = fmaxf(acc.z * dn + b.z, 0.f);
    acc.w = fmaxf(acc.w * dn + b.w, 0.f);

    if (FUSE_GEMV) {
        float4 w = ((const float4*)W3)[lane];
        float dot = acc.x * w.x + acc.y * w.y + acc.z * w.z + acc.w * w.w;
        #pragma unroll
        for (int off = 16; off > 0; off >>= 1)
            dot += __shfl_down_sync(0xFFFFFFFFu, dot, off);
        if (lane == 0) g_hw3[node] = dot * dn;
    } else {
        ((float4*)(OUT + (size_t)node * D))[lane] = acc;
    }
}

// ---------------- layer 3: scalar aggregation -----------------------------
__global__ void agg3_kernel(const float* __restrict__ b3, float* __restrict__ OUT) {
    int node = blockIdx.x * blockDim.x + threadIdx.x;
    if (node >= N_NODES) return;
    float acc = g_hw3[node];
    int beg = g_base[node];
    int end = beg + g_counts[node];
    for (int e = beg; e < end; e++)
        acc += g_hw3[__ldg(&g_csr_src[e])];
    OUT[node] = fmaxf(acc * g_dis[node] + b3[0], 0.f);
}

// ---------------- launch ---------------------------------------------------
extern "C" void kernel_launch(void* const* d_in, const int* in_sizes, int n_in,
                              void* d_out, int out_size) {
    const float* x  = (const float*)d_in[0];
    const int*   ei = (const int*)d_in[1];
    const float* W1 = (const float*)d_in[2];
    const float* b1 = (const float*)d_in[3];
    const float* W2 = (const float*)d_in[4];
    const float* b2 = (const float*)d_in[5];
    const float* W3 = (const float*)d_in[6];
    const float* b3 = (const float*)d_in[7];
    float* out = (float*)d_out;

    const int* src = ei;
    const int* dst = ei + N_EDGES;

    __half* hw;  cudaGetSymbolAddress((void**)&hw,  g_hw);
    float*  act; cudaGetSymbolAddress((void**)&act, g_act);
    int* counts; cudaGetSymbolAddress((void**)&counts, g_counts);
    int* total;  cudaGetSymbolAddress((void**)&total,  g_total);

    int nb_nodes = (N_NODES + 255) / 256;
    int nb_edge4 = (N_EDGES / 4 + 255) / 256;
    int nb_warp  = (N_NODES * 32 + 255) / 256;
    dim3 gemm_grid((N_NODES + 127) / 128, 2);

    // preprocessing: unordered CSR by dst
    cudaMemsetAsync(counts, 0, N_NODES * sizeof(int));
    cudaMemsetAsync(total, 0, sizeof(int));
    hist_kernel<<<nb_edge4, 256>>>(dst);
    prefix_kernel<<<nb_nodes, 256>>>();
    scatter_kernel<<<nb_edge4, 256>>>(src, dst);

    // layer 1
    gemm_tf32_kernel<<<gemm_grid, 256>>>(x, W1, hw, N_NODES);
    agg128_kernel<false><<<nb_warp, 256>>>(hw, b1, act, nullptr);
    // layer 2 (+ fused layer-3 GEMV)
    gemm_tf32_kernel<<<gemm_grid, 256>>>(act, W2, hw, N_NODES);
    agg128_kernel<true><<<nb_warp, 256>>>(hw, b2, nullptr, W3);
    // layer 3 aggregation
    agg3_kernel<<<nb_nodes, 256>>>(b3, out);
}